// round 11
// baseline (speedup 1.0000x reference)
#include <cuda_runtime.h>

#define BATCH   4096
#define FEAT    40960
#define ACCUM   512
#define H1      32
#define MAXIDX  128
#define TFEAT   64
#define TACC    32
#define NTILES  ((FEAT / TFEAT) * (ACCUM / TACC))   // 640*16 = 10240

// Scratch (device globals — no allocations allowed)
__device__ float g_ftT[(size_t)FEAT * ACCUM];   // transposed ft weights [FEAT][ACCUM]
__device__ int   g_tile;    // transpose tile queue (reset by last block)
__device__ int   g_done;    // completed tiles (release/acquire)
__device__ int   g_fin;     // finished blocks (for counter reset)

// ---------------------------------------------------------------------------
// Single fused kernel. One block per batch row, 512 threads, 4 CTAs/SM.
//  - per-block stm dtype detection (2 iters, L2-hit after wave 1)
//  - transpose tiles work-stolen between 5-iteration scan chunks
//  - release/acquire on g_done before the gather phase
//  - last finishing block resets the global counters for the next replay
// ---------------------------------------------------------------------------
__global__ __launch_bounds__(512, 4) void nnue_kernel(
    const float* __restrict__ wf, const float* __restrict__ bf,
    const unsigned char* __restrict__ stm_raw,
    const float* __restrict__ ftw,
    const float* __restrict__ ft_b,
    const float* __restrict__ l1_w, const float* __restrict__ l1_b,
    const float* __restrict__ l2_w, const float* __restrict__ l2_b,
    const float* __restrict__ out_w, const float* __restrict__ out_b,
    float* __restrict__ out)
{
    const int row = blockIdx.x;
    const int t   = threadIdx.x;

    __shared__ float  tile[TFEAT][TACC + 1];     // transpose staging (8.3 KB)
    __shared__ float4 sp[4][ACCUM / 4];          // gather partials (8 KB)
    __shared__ int    idxw[MAXIDX], idxb[MAXIDX];
    __shared__ int    nw, nb, claim, bad_int, bad_f32;
    __shared__ float  x[2 * ACCUM];
    __shared__ float  v1s[H1];

    if (t == 0) { nw = 0; nb = 0; bad_int = 0; bad_f32 = 0; }
    __syncthreads();

    // ---- stm dtype detection (first 4096 bytes are safe to read under
    //      byte-bool / int32 / float32 alike) ----
    #pragma unroll
    for (int gdx = 0; gdx < 2; gdx++) {
        int g4 = t + gdx * 512;
        unsigned char b0 = stm_raw[4*g4+0], b1 = stm_raw[4*g4+1];
        unsigned char b2 = stm_raw[4*g4+2], b3 = stm_raw[4*g4+3];
        if (!((b1 | b2 | b3) == 0 && b0 <= 1)) atomicOr(&bad_int, 1);
        bool zero = (b0 | b1 | b2 | b3) == 0;
        bool one  = (b0 == 0 && b1 == 0 && b2 == 0x80 && b3 == 0x3F);
        if (!(zero || one)) atomicOr(&bad_f32, 1);
    }

    // ---- scan + transpose interleave ----
    const float4* wrow = (const float4*)(wf + (size_t)row * FEAT);
    const float4* brow = (const float4*)(bf + (size_t)row * FEAT);

    int  my_tiles = 0;
    bool qempty = false;

    // one stolen tile (all-thread uniform control flow)
    #define DO_TILE()                                                          \
    do {                                                                       \
        __syncthreads();                                                       \
        if (t == 0) claim = atomicAdd(&g_tile, 1);                             \
        __syncthreads();                                                       \
        int tl = claim;                                                        \
        if (tl >= NTILES) { qempty = true; break; }                            \
        int fx = (tl % (FEAT / TFEAT)) * TFEAT;                                \
        int oy = (tl / (FEAT / TFEAT)) * TACC;                                 \
        {   int a = t >> 4, q = t & 15;                                        \
            float4 v = __ldcs((const float4*)&ftw[(size_t)(oy + a) * FEAT + fx + 4*q]); \
            tile[4*q + 0][a] = v.x; tile[4*q + 1][a] = v.y;                    \
            tile[4*q + 2][a] = v.z; tile[4*q + 3][a] = v.w; }                  \
        __syncthreads();                                                       \
        {   int f = t >> 3, q = t & 7;                                         \
            float4 o;                                                          \
            o.x = tile[f][4*q + 0]; o.y = tile[f][4*q + 1];                    \
            o.z = tile[f][4*q + 2]; o.w = tile[f][4*q + 3];                    \
            *(float4*)&g_ftT[(size_t)(fx + f) * ACCUM + oy + 4*q] = o; }       \
        my_tiles++;                                                            \
    } while (0)

    #define SCAN_W(i)                                                          \
    {   int vi = t + (i) * 512;                                                \
        float4 v = __ldcs(&wrow[vi]);                                          \
        if (v.x != 0.f) { int p = atomicAdd(&nw, 1); if (p < MAXIDX) idxw[p] = 4*vi + 0; } \
        if (v.y != 0.f) { int p = atomicAdd(&nw, 1); if (p < MAXIDX) idxw[p] = 4*vi + 1; } \
        if (v.z != 0.f) { int p = atomicAdd(&nw, 1); if (p < MAXIDX) idxw[p] = 4*vi + 2; } \
        if (v.w != 0.f) { int p = atomicAdd(&nw, 1); if (p < MAXIDX) idxw[p] = 4*vi + 3; } }

    #define SCAN_B(i)                                                          \
    {   int vi = t + (i) * 512;                                                \
        float4 u = __ldcs(&brow[vi]);                                          \
        if (u.x != 0.f) { int p = atomicAdd(&nb, 1); if (p < MAXIDX) idxb[p] = 4*vi + 0; } \
        if (u.y != 0.f) { int p = atomicAdd(&nb, 1); if (p < MAXIDX) idxb[p] = 4*vi + 1; } \
        if (u.z != 0.f) { int p = atomicAdd(&nb, 1); if (p < MAXIDX) idxb[p] = 4*vi + 2; } \
        if (u.w != 0.f) { int p = atomicAdd(&nb, 1); if (p < MAXIDX) idxb[p] = 4*vi + 3; } }

    #pragma unroll 1
    for (int c = 0; c < 4; c++) {            // white: 4 chunks x 5 iters
        #pragma unroll
        for (int j = 0; j < 5; j++) SCAN_W(c * 5 + j);
        for (int r = 0; r < 3 && !qempty; r++) DO_TILE();
    }
    #pragma unroll 1
    for (int c = 0; c < 4; c++) {            // black: 4 chunks x 5 iters
        #pragma unroll
        for (int j = 0; j < 5; j++) SCAN_B(c * 5 + j);
        for (int r = 0; r < 3 && !qempty; r++) DO_TILE();
    }
    while (!qempty) DO_TILE();               // drain any leftovers

    // release this block's completed tiles
    __syncthreads();
    if (t == 0 && my_tiles > 0) {
        __threadfence();
        atomicAdd(&g_done, my_tiles);
    }

    // acquire-wait: all tiles transposed before gather
    if (t == 0) {
        for (;;) {
            int d;
            asm volatile("ld.acquire.gpu.global.b32 %0, [%1];" : "=r"(d) : "l"(&g_done));
            if (d >= NTILES) break;
            __nanosleep(64);
        }
    }
    __syncthreads();

    const int cw = min(nw, MAXIDX), cb = min(nb, MAXIDX);
    const int g = t >> 7;        // gather group 0..3
    const int u = t & 127;       // channel block: channels 4u..4u+3
    const float* spf = (const float*)sp;

    // ---- white gather (float4, grouped) ----
    {
        float4 s0 = {0.f,0.f,0.f,0.f}, s1 = {0.f,0.f,0.f,0.f};
        int k = g;
        #pragma unroll 1
        for (; k + 4 < cw; k += 8) {
            float4 va = *(const float4*)&g_ftT[(size_t)idxw[k]     * ACCUM + 4*u];
            float4 vb = *(const float4*)&g_ftT[(size_t)idxw[k + 4] * ACCUM + 4*u];
            s0.x += va.x; s0.y += va.y; s0.z += va.z; s0.w += va.w;
            s1.x += vb.x; s1.y += vb.y; s1.z += vb.z; s1.w += vb.w;
        }
        if (k < cw) {
            float4 va = *(const float4*)&g_ftT[(size_t)idxw[k] * ACCUM + 4*u];
            s0.x += va.x; s0.y += va.y; s0.z += va.z; s0.w += va.w;
        }
        s0.x += s1.x; s0.y += s1.y; s0.z += s1.z; s0.w += s1.w;
        sp[g][u] = s0;
    }
    __syncthreads();
    float accw = ft_b[t] + (spf[0*ACCUM + t] + spf[1*ACCUM + t])
                         + (spf[2*ACCUM + t] + spf[3*ACCUM + t]);
    __syncthreads();

    // ---- black gather ----
    {
        float4 s0 = {0.f,0.f,0.f,0.f}, s1 = {0.f,0.f,0.f,0.f};
        int k = g;
        #pragma unroll 1
        for (; k + 4 < cb; k += 8) {
            float4 va = *(const float4*)&g_ftT[(size_t)idxb[k]     * ACCUM + 4*u];
            float4 vb = *(const float4*)&g_ftT[(size_t)idxb[k + 4] * ACCUM + 4*u];
            s0.x += va.x; s0.y += va.y; s0.z += va.z; s0.w += va.w;
            s1.x += vb.x; s1.y += vb.y; s1.z += vb.z; s1.w += vb.w;
        }
        if (k < cb) {
            float4 va = *(const float4*)&g_ftT[(size_t)idxb[k] * ACCUM + 4*u];
            s0.x += va.x; s0.y += va.y; s0.z += va.z; s0.w += va.w;
        }
        s0.x += s1.x; s0.y += s1.y; s0.z += s1.z; s0.w += s1.w;
        sp[g][u] = s0;
    }
    __syncthreads();
    float accb = ft_b[t] + (spf[0*ACCUM + t] + spf[1*ACCUM + t])
                         + (spf[2*ACCUM + t] + spf[3*ACCUM + t]);

    // screlu
    accw = fminf(fmaxf(accw, 0.f), 1.f); accw *= accw;
    accb = fminf(fmaxf(accb, 0.f), 1.f); accb *= accb;

    // stm select (per-block detected dtype)
    bool s;
    {
        int mode = (!bad_int) ? 1 : ((!bad_f32) ? 2 : 0);
        if (mode == 1)      s = ((const int*)stm_raw)[row] != 0;
        else if (mode == 2) s = ((const float*)stm_raw)[row] != 0.f;
        else                s = stm_raw[row] != 0;
    }
    x[t]         = s ? accb : accw;
    x[ACCUM + t] = s ? accw : accb;
    __syncthreads();

    // ---- L1 (32 outputs x 1024 dot), 16 warps x 2 outputs ----
    const int warp = t >> 5, lane = t & 31;
    #pragma unroll
    for (int oo = 0; oo < 2; oo++) {
        int o = warp * 2 + oo;
        const float* w1 = l1_w + (size_t)o * (2 * ACCUM);
        float sum = 0.f;
        #pragma unroll
        for (int j = lane; j < 2 * ACCUM; j += 32)
            sum += x[j] * __ldg(&w1[j]);
        #pragma unroll
        for (int off = 16; off > 0; off >>= 1)
            sum += __shfl_down_sync(0xffffffffu, sum, off);
        if (lane == 0) {
            sum += l1_b[o];
            sum = fminf(fmaxf(sum, 0.f), 1.f);
            v1s[o] = sum * sum;
        }
    }
    __syncthreads();

    // ---- L2 layer + output head (warp 0) ----
    if (warp == 0) {
        float sum = l2_b[lane];
        #pragma unroll
        for (int j = 0; j < H1; j++)
            sum += v1s[j] * __ldg(&l2_w[lane * H1 + j]);
        sum = fminf(fmaxf(sum, 0.f), 1.f);
        float vv = sum * sum * __ldg(&out_w[lane]);
        #pragma unroll
        for (int off = 16; off > 0; off >>= 1)
            vv += __shfl_down_sync(0xffffffffu, vv, off);
        if (lane == 0) out[row] = vv + out_b[0];
    }

    // ---- last block resets the work-queue counters for the next replay ----
    __syncthreads();
    if (t == 0) {
        __threadfence();
        int f = atomicAdd(&g_fin, 1);
        if (f == (int)gridDim.x - 1) {
            g_tile = 0;
            g_done = 0;
            g_fin  = 0;
        }
    }
}

// ---------------------------------------------------------------------------
extern "C" void kernel_launch(void* const* d_in, const int* in_sizes, int n_in,
                              void* d_out, int out_size) {
    const float*         wf    = (const float*)d_in[0];
    const float*         bf    = (const float*)d_in[1];
    const unsigned char* stm   = (const unsigned char*)d_in[2];
    const float*         ft_w  = (const float*)d_in[3];
    const float*         ft_b  = (const float*)d_in[4];
    const float*         l1_w  = (const float*)d_in[5];
    const float*         l1_b  = (const float*)d_in[6];
    const float*         l2_w  = (const float*)d_in[7];
    const float*         l2_b  = (const float*)d_in[8];
    const float*         out_w = (const float*)d_in[9];
    const float*         out_b = (const float*)d_in[10];
    float*               out   = (float*)d_out;

    nnue_kernel<<<BATCH, 512>>>(wf, bf, stm, ft_w, ft_b, l1_w, l1_b,
                                l2_w, l2_b, out_w, out_b, out);
}

// round 12
// speedup vs baseline: 1.2374x; 1.2374x over previous
#include <cuda_runtime.h>
#include <cuda_fp16.h>

#define BATCH   4096
#define FEAT    40960
#define ACCUM   512
#define H1      32
#define MAXIDX  128

// Scratch (device globals — no allocations allowed)
__device__ __half g_ftTh[(size_t)FEAT * ACCUM];   // transposed fp16 weights [FEAT][ACCUM] (42 MB, L2-resident)
__device__ int    g_stm_mode;                     // 0 = byte bool, 1 = int32, 2 = float32

// ---------------------------------------------------------------------------
// K1: transpose + fp32->fp16 convert: ft_w [ACCUM, FEAT] -> g_ftTh [FEAT, ACCUM].
// Tile = 64 feat x 32 accum, 512 threads.
//   load : thread t reads 4 feats of one accum row (LDG.128, __ldcs)
//   store: threads 0..255 write 8 accum chans (as 4x half2 = 16B, STG.128)
// Store-side smem reads are conflict-free: bank(f*33 + 8q+i) = f+8q+i spans 32.
// Block (0,0) additionally detects the stm dtype (first 4096 bytes only).
// ---------------------------------------------------------------------------
__global__ __launch_bounds__(512) void transpose_kernel(
    const float* __restrict__ ftw,
    const unsigned char* __restrict__ stm)
{
    __shared__ float tile[64][33];
    __shared__ int bad_int, bad_f32;

    const int t = threadIdx.x;
    const bool detect = (blockIdx.x == 0 && blockIdx.y == 0);

    if (detect) {
        if (t == 0) { bad_int = 0; bad_f32 = 0; }
        __syncthreads();
        for (int g = t; g < 1024; g += 512) {
            unsigned char b0 = stm[4*g+0], b1 = stm[4*g+1];
            unsigned char b2 = stm[4*g+2], b3 = stm[4*g+3];
            if (!((b1 | b2 | b3) == 0 && b0 <= 1)) atomicOr(&bad_int, 1);
            bool zero = (b0 | b1 | b2 | b3) == 0;
            bool one  = (b0 == 0 && b1 == 0 && b2 == 0x80 && b3 == 0x3F);
            if (!(zero || one)) atomicOr(&bad_f32, 1);
        }
        __syncthreads();
        if (t == 0)
            g_stm_mode = (!bad_int) ? 1 : ((!bad_f32) ? 2 : 0);
        __syncthreads();
    }

    const int fx = blockIdx.x * 64;    // feature tile origin
    const int oy = blockIdx.y * 32;    // accum tile origin

    // Load: a = accum row (0..31), q = feat quad (0..15)
    {
        int a = t >> 4, q = t & 15;
        float4 v = __ldcs((const float4*)&ftw[(size_t)(oy + a) * FEAT + fx + 4*q]);
        tile[4*q + 0][a] = v.x;
        tile[4*q + 1][a] = v.y;
        tile[4*q + 2][a] = v.z;
        tile[4*q + 3][a] = v.w;
    }
    __syncthreads();

    // Store: f = feat row (0..63), q = accum octet (0..3) -> 8 halves = 16B
    if (t < 256) {
        int f = t >> 2, q = t & 3;
        __half2 h0 = __floats2half2_rn(tile[f][8*q + 0], tile[f][8*q + 1]);
        __half2 h1 = __floats2half2_rn(tile[f][8*q + 2], tile[f][8*q + 3]);
        __half2 h2 = __floats2half2_rn(tile[f][8*q + 4], tile[f][8*q + 5]);
        __half2 h3 = __floats2half2_rn(tile[f][8*q + 6], tile[f][8*q + 7]);
        uint4 o;
        o.x = *reinterpret_cast<unsigned*>(&h0);
        o.y = *reinterpret_cast<unsigned*>(&h1);
        o.z = *reinterpret_cast<unsigned*>(&h2);
        o.w = *reinterpret_cast<unsigned*>(&h3);
        *(uint4*)&g_ftTh[(size_t)(fx + f) * ACCUM + oy + 8*q] = o;
    }
}

// ---------------------------------------------------------------------------
// K2: NNUE forward. One block per batch row, 512 threads, 4 CTAs/SM.
// Scan: R9-proven (__ldcs, full unroll, uninterrupted).
// Gather: 8 groups x 64 threads; thread owns 8 channels via one uint4
// (8 halves) per feature; fp32 accumulation; smem cross-group reduction.
// ---------------------------------------------------------------------------
__global__ __launch_bounds__(512, 4) void nnue_kernel(
    const float* __restrict__ wf, const float* __restrict__ bf,
    const unsigned char* __restrict__ stm_raw,
    const float* __restrict__ ft_b,
    const float* __restrict__ l1_w, const float* __restrict__ l1_b,
    const float* __restrict__ l2_w, const float* __restrict__ l2_b,
    const float* __restrict__ out_w, const float* __restrict__ out_b,
    float* __restrict__ out)
{
    const int row = blockIdx.x;
    const int t   = threadIdx.x;

    __shared__ float sp[8][ACCUM];     // gather partials (16 KB)
    __shared__ int   idxw[MAXIDX], idxb[MAXIDX];
    __shared__ int   nw, nb;
    __shared__ float x[2 * ACCUM];
    __shared__ float v1s[H1];

    if (t == 0) { nw = 0; nb = 0; }
    __syncthreads();

    // ---- Phase A: scan features — white pass, then black pass ----
    const float4* wrow = (const float4*)(wf + (size_t)row * FEAT);
    const float4* brow = (const float4*)(bf + (size_t)row * FEAT);

    #pragma unroll
    for (int i = 0; i < FEAT / 4 / 512; i++) {   // 20 iterations
        int vi = t + i * 512;
        float4 v = __ldcs(&wrow[vi]);
        if (v.x != 0.f) { int p = atomicAdd(&nw, 1); if (p < MAXIDX) idxw[p] = 4*vi + 0; }
        if (v.y != 0.f) { int p = atomicAdd(&nw, 1); if (p < MAXIDX) idxw[p] = 4*vi + 1; }
        if (v.z != 0.f) { int p = atomicAdd(&nw, 1); if (p < MAXIDX) idxw[p] = 4*vi + 2; }
        if (v.w != 0.f) { int p = atomicAdd(&nw, 1); if (p < MAXIDX) idxw[p] = 4*vi + 3; }
    }
    #pragma unroll
    for (int i = 0; i < FEAT / 4 / 512; i++) {   // 20 iterations
        int vi = t + i * 512;
        float4 u = __ldcs(&brow[vi]);
        if (u.x != 0.f) { int p = atomicAdd(&nb, 1); if (p < MAXIDX) idxb[p] = 4*vi + 0; }
        if (u.y != 0.f) { int p = atomicAdd(&nb, 1); if (p < MAXIDX) idxb[p] = 4*vi + 1; }
        if (u.z != 0.f) { int p = atomicAdd(&nb, 1); if (p < MAXIDX) idxb[p] = 4*vi + 2; }
        if (u.w != 0.f) { int p = atomicAdd(&nb, 1); if (p < MAXIDX) idxb[p] = 4*vi + 3; }
    }
    __syncthreads();

    const int cw = min(nw, MAXIDX), cb = min(nb, MAXIDX);

    const int g = t >> 6;        // gather group 0..7 (feature stride)
    const int u = t & 63;        // channel octet: channels 8u..8u+7

    // ---- Phase B1: white gather ----
    {
        float s0=0.f,s1=0.f,s2=0.f,s3=0.f,s4=0.f,s5=0.f,s6=0.f,s7=0.f;
        #pragma unroll 1
        for (int k = g; k < cw; k += 8) {
            uint4 v = *(const uint4*)&g_ftTh[(size_t)idxw[k] * ACCUM + 8*u];
            float2 f0 = __half22float2(*reinterpret_cast<__half2*>(&v.x));
            float2 f1 = __half22float2(*reinterpret_cast<__half2*>(&v.y));
            float2 f2 = __half22float2(*reinterpret_cast<__half2*>(&v.z));
            float2 f3 = __half22float2(*reinterpret_cast<__half2*>(&v.w));
            s0 += f0.x; s1 += f0.y; s2 += f1.x; s3 += f1.y;
            s4 += f2.x; s5 += f2.y; s6 += f3.x; s7 += f3.y;
        }
        sp[g][8*u + 0] = s0; sp[g][8*u + 1] = s1;
        sp[g][8*u + 2] = s2; sp[g][8*u + 3] = s3;
        sp[g][8*u + 4] = s4; sp[g][8*u + 5] = s5;
        sp[g][8*u + 6] = s6; sp[g][8*u + 7] = s7;
    }
    __syncthreads();
    float accw = ft_b[t] + ((sp[0][t] + sp[1][t]) + (sp[2][t] + sp[3][t]))
                         + ((sp[4][t] + sp[5][t]) + (sp[6][t] + sp[7][t]));
    __syncthreads();

    // ---- Phase B2: black gather ----
    {
        float s0=0.f,s1=0.f,s2=0.f,s3=0.f,s4=0.f,s5=0.f,s6=0.f,s7=0.f;
        #pragma unroll 1
        for (int k = g; k < cb; k += 8) {
            uint4 v = *(const uint4*)&g_ftTh[(size_t)idxb[k] * ACCUM + 8*u];
            float2 f0 = __half22float2(*reinterpret_cast<__half2*>(&v.x));
            float2 f1 = __half22float2(*reinterpret_cast<__half2*>(&v.y));
            float2 f2 = __half22float2(*reinterpret_cast<__half2*>(&v.z));
            float2 f3 = __half22float2(*reinterpret_cast<__half2*>(&v.w));
            s0 += f0.x; s1 += f0.y; s2 += f1.x; s3 += f1.y;
            s4 += f2.x; s5 += f2.y; s6 += f3.x; s7 += f3.y;
        }
        sp[g][8*u + 0] = s0; sp[g][8*u + 1] = s1;
        sp[g][8*u + 2] = s2; sp[g][8*u + 3] = s3;
        sp[g][8*u + 4] = s4; sp[g][8*u + 5] = s5;
        sp[g][8*u + 6] = s6; sp[g][8*u + 7] = s7;
    }
    __syncthreads();
    float accb = ft_b[t] + ((sp[0][t] + sp[1][t]) + (sp[2][t] + sp[3][t]))
                         + ((sp[4][t] + sp[5][t]) + (sp[6][t] + sp[7][t]));

    // screlu
    accw = fminf(fmaxf(accw, 0.f), 1.f); accw *= accw;
    accb = fminf(fmaxf(accb, 0.f), 1.f); accb *= accb;

    // stm select (dtype-mode decoded)
    bool s;
    {
        int mode = g_stm_mode;
        if (mode == 1)      s = ((const int*)stm_raw)[row] != 0;
        else if (mode == 2) s = ((const float*)stm_raw)[row] != 0.f;
        else                s = stm_raw[row] != 0;
    }
    x[t]         = s ? accb : accw;
    x[ACCUM + t] = s ? accw : accb;
    __syncthreads();

    // ---- Phase C: L1 (32 outputs x 1024 dot), 16 warps x 2 outputs ----
    const int warp = t >> 5, lane = t & 31;
    #pragma unroll
    for (int oo = 0; oo < 2; oo++) {
        int o = warp * 2 + oo;
        const float* w1 = l1_w + (size_t)o * (2 * ACCUM);
        float sum = 0.f;
        #pragma unroll
        for (int j = lane; j < 2 * ACCUM; j += 32)
            sum += x[j] * __ldg(&w1[j]);
        #pragma unroll
        for (int off = 16; off > 0; off >>= 1)
            sum += __shfl_down_sync(0xffffffffu, sum, off);
        if (lane == 0) {
            sum += l1_b[o];
            sum = fminf(fmaxf(sum, 0.f), 1.f);
            v1s[o] = sum * sum;
        }
    }
    __syncthreads();

    // ---- L2 layer + output head (warp 0) ----
    if (warp == 0) {
        float sum = l2_b[lane];
        #pragma unroll
        for (int j = 0; j < H1; j++)
            sum += v1s[j] * __ldg(&l2_w[lane * H1 + j]);
        sum = fminf(fmaxf(sum, 0.f), 1.f);
        float vv = sum * sum * __ldg(&out_w[lane]);
        #pragma unroll
        for (int off = 16; off > 0; off >>= 1)
            vv += __shfl_down_sync(0xffffffffu, vv, off);
        if (lane == 0) out[row] = vv + out_b[0];
    }
}

// ---------------------------------------------------------------------------
extern "C" void kernel_launch(void* const* d_in, const int* in_sizes, int n_in,
                              void* d_out, int out_size) {
    const float*         wf    = (const float*)d_in[0];
    const float*         bf    = (const float*)d_in[1];
    const unsigned char* stm   = (const unsigned char*)d_in[2];
    const float*         ft_w  = (const float*)d_in[3];
    const float*         ft_b  = (const float*)d_in[4];
    const float*         l1_w  = (const float*)d_in[5];
    const float*         l1_b  = (const float*)d_in[6];
    const float*         l2_w  = (const float*)d_in[7];
    const float*         l2_b  = (const float*)d_in[8];
    const float*         out_w = (const float*)d_in[9];
    const float*         out_b = (const float*)d_in[10];
    float*               out   = (float*)d_out;

    dim3 tgrid(FEAT / 64, ACCUM / 32);
    transpose_kernel<<<tgrid, 512>>>(ft_w, stm);

    nnue_kernel<<<BATCH, 512>>>(wf, bf, stm, ft_b, l1_w, l1_b,
                                l2_w, l2_b, out_w, out_b, out);
}